// round 2
// baseline (speedup 1.0000x reference)
#include <cuda_runtime.h>
#include <math.h>

#define DDIM 768
#define SLEN 512
#define BATCH 64
#define NROWS (BATCH * SLEN)   // 32768
#define EPSV 1e-8f

// ---- scratch (allocation-free: __device__ globals) ----
__device__ __align__(16) float g_protoSum[DDIM];
__device__ __align__(16) float g_proto[DDIM];
__device__ float g_protoNorm;
__device__ int   g_entCount;
__device__ int   g_nzCount;
__device__ float g_simSum;
__device__ int   g_isI64;      // 1 if labels buffer is int64, 0 if int32

// Dual-dtype label fetch. Values are small (0..9) so int range is safe.
__device__ __forceinline__ int load_label(const void* __restrict__ labels, int r) {
    if (g_isI64) return (int)((const long long*)labels)[r];
    return ((const int*)labels)[r];
}

// ---------------------------------------------------------------------------
// K0: zero accumulators + detect labels dtype.
// int64 little-endian => all odd int32 words (high words) are 0 for labels
// in [0,10). int32 => odd words are random labels, ~90% nonzero. Reading
// int32 indices < NROWS is safe under either interpretation.
// One block, 768 threads.
// ---------------------------------------------------------------------------
__global__ void k_init(const int* __restrict__ labels32) {
    __shared__ int s_any;
    const int tid = threadIdx.x;
    if (tid < DDIM) g_protoSum[tid] = 0.0f;
    if (tid == 0) {
        g_entCount = 0;
        g_nzCount = 0;
        g_simSum = 0.0f;
        g_protoNorm = 0.0f;
        s_any = 0;
    }
    __syncthreads();
    int any = 0;
    for (int i = 1 + 2 * tid; i < NROWS; i += 2 * blockDim.x)
        any |= labels32[i];
    if (any) atomicOr(&s_any, 1);
    __syncthreads();
    if (tid == 0) g_isI64 = (s_any == 0);
}

// ---------------------------------------------------------------------------
// K1: accumulate proto sum over rows with label==entity_id && s!=0.
// 256 blocks x 256 threads; block owns 128 consecutive rows.
// Only entity rows are read from HBM (~10% of logits).
// ---------------------------------------------------------------------------
__global__ void k_proto_accum(const float* __restrict__ logits,
                              const void* __restrict__ labels,
                              const int* __restrict__ entity_ptr) {
    __shared__ float s_acc[DDIM];
    const int tid = threadIdx.x;
    const int entity_id = *entity_ptr;   // low 32 bits valid for i32 or i64
    for (int d = tid; d < DDIM; d += 256) s_acc[d] = 0.0f;
    __syncthreads();

    const int row0 = blockIdx.x * 128;
    int ent_local = 0;

    for (int i = 0; i < 128; ++i) {
        const int r = row0 + i;
        const int s = r & (SLEN - 1);
        const int lab = load_label(labels, r);
        if (lab == entity_id && s != 0) {
            if (tid == 0) ent_local++;
            const float* __restrict__ row = logits + (size_t)r * DDIM;
            s_acc[tid]       += row[tid];
            s_acc[tid + 256] += row[tid + 256];
            s_acc[tid + 512] += row[tid + 512];
        }
    }
    __syncthreads();
    for (int d = tid; d < DDIM; d += 256)
        atomicAdd(&g_protoSum[d], s_acc[d]);
    if (tid == 0 && ent_local > 0)
        atomicAdd(&g_entCount, ent_local);
}

// ---------------------------------------------------------------------------
// K2: finalize proto and its L2 norm. One block, 256 threads.
// ---------------------------------------------------------------------------
__global__ void k_proto_final() {
    __shared__ float s_red[256];
    const int tid = threadIdx.x;
    const float inv = 1.0f / fmaxf((float)g_entCount, 1.0f);
    float ss = 0.0f;
    for (int d = tid; d < DDIM; d += 256) {
        float p = g_protoSum[d] * inv;
        g_proto[d] = p;
        ss += p * p;
    }
    s_red[tid] = ss;
    __syncthreads();
    for (int off = 128; off > 0; off >>= 1) {
        if (tid < off) s_red[tid] += s_red[tid + off];
        __syncthreads();
    }
    if (tid == 0) g_protoNorm = sqrtf(s_red[0]);
}

// ---------------------------------------------------------------------------
// K3 (hot): one warp per row, 8 rows per warp, proto held in registers.
// dot(row,proto) and ||row||^2 in a single pass over the row.
// Rows with label==0 are skipped (no HBM read).
// 512 blocks x 256 threads = 4096 warps x 8 rows = 32768 rows.
// ---------------------------------------------------------------------------
__global__ __launch_bounds__(256) void k_main(const float* __restrict__ logits,
                                              const void* __restrict__ labels) {
    const int tid  = threadIdx.x;
    const int lane = tid & 31;
    const int warp = tid >> 5;
    const int gw   = blockIdx.x * 8 + warp;     // 0..4095

    // proto in registers: 6 float4 per lane
    const float4* __restrict__ proto4 = (const float4*)g_proto;
    float4 p0 = proto4[lane];
    float4 p1 = proto4[lane + 32];
    float4 p2 = proto4[lane + 64];
    float4 p3 = proto4[lane + 96];
    float4 p4 = proto4[lane + 128];
    float4 p5 = proto4[lane + 160];
    const float protoNorm = g_protoNorm;

    float simLocal = 0.0f;
    int   nzLocal  = 0;

    #pragma unroll 1
    for (int k = 0; k < 8; ++k) {
        const int row = gw * 8 + k;
        const int lab = load_label(labels, row);
        if (lab == 0) continue;
        nzLocal++;   // uniform branch: every lane counts identically

        const float4* __restrict__ row4 =
            (const float4*)(logits + (size_t)row * DDIM);
        float4 v0 = row4[lane];
        float4 v1 = row4[lane + 32];
        float4 v2 = row4[lane + 64];
        float4 v3 = row4[lane + 96];
        float4 v4 = row4[lane + 128];
        float4 v5 = row4[lane + 160];

        float dot =
            v0.x*p0.x + v0.y*p0.y + v0.z*p0.z + v0.w*p0.w +
            v1.x*p1.x + v1.y*p1.y + v1.z*p1.z + v1.w*p1.w +
            v2.x*p2.x + v2.y*p2.y + v2.z*p2.z + v2.w*p2.w +
            v3.x*p3.x + v3.y*p3.y + v3.z*p3.z + v3.w*p3.w +
            v4.x*p4.x + v4.y*p4.y + v4.z*p4.z + v4.w*p4.w +
            v5.x*p5.x + v5.y*p5.y + v5.z*p5.z + v5.w*p5.w;
        float nrm =
            v0.x*v0.x + v0.y*v0.y + v0.z*v0.z + v0.w*v0.w +
            v1.x*v1.x + v1.y*v1.y + v1.z*v1.z + v1.w*v1.w +
            v2.x*v2.x + v2.y*v2.y + v2.z*v2.z + v2.w*v2.w +
            v3.x*v3.x + v3.y*v3.y + v3.z*v3.z + v3.w*v3.w +
            v4.x*v4.x + v4.y*v4.y + v4.z*v4.z + v4.w*v4.w +
            v5.x*v5.x + v5.y*v5.y + v5.z*v5.z + v5.w*v5.w;

        #pragma unroll
        for (int off = 16; off > 0; off >>= 1) {
            dot += __shfl_xor_sync(0xFFFFFFFFu, dot, off);
            nrm += __shfl_xor_sync(0xFFFFFFFFu, nrm, off);
        }
        if (lane == 0) {
            float denom = fmaxf(sqrtf(nrm) * protoNorm, EPSV);
            simLocal += dot / denom;
        }
    }

    __shared__ float s_sum[8];
    __shared__ int   s_nz[8];
    if (lane == 0) {
        s_sum[warp] = simLocal;
        s_nz[warp]  = nzLocal;
    }
    __syncthreads();
    if (warp == 0 && lane == 0) {
        float bs = 0.0f; int bn = 0;
        #pragma unroll
        for (int i = 0; i < 8; ++i) { bs += s_sum[i]; bn += s_nz[i]; }
        if (bs != 0.0f || bn != 0) {
            atomicAdd(&g_simSum, bs);
            atomicAdd(&g_nzCount, bn);
        }
    }
}

// ---------------------------------------------------------------------------
// K4: final divide
// ---------------------------------------------------------------------------
__global__ void k_final(float* __restrict__ d_out) {
    d_out[0] = g_simSum / fmaxf((float)g_nzCount, 1.0f);
}

extern "C" void kernel_launch(void* const* d_in, const int* in_sizes, int n_in,
                              void* d_out, int out_size) {
    const float* logits     = (const float*)d_in[0];
    const void*  labels     = d_in[1];
    const int*   entity_ptr = (const int*)d_in[2];
    (void)n_in; (void)in_sizes; (void)out_size;

    k_init<<<1, 768>>>((const int*)labels);
    k_proto_accum<<<256, 256>>>(logits, labels, entity_ptr);
    k_proto_final<<<1, 256>>>();
    k_main<<<512, 256>>>(logits, labels);
    k_final<<<1, 1>>>((float*)d_out);
}

// round 3
// speedup vs baseline: 1.7465x; 1.7465x over previous
#include <cuda_runtime.h>
#include <math.h>

#define DDIM  768
#define SLEN  512
#define NROWS 32768
#define EPSV  1e-8f

#define PROTO_BLOCKS 256   // x 256 thr, warp = 16 rows
#define MAIN_BLOCKS  1024  // x 128 thr, warp = 8 rows

// ---- scratch (allocation-free; zero-initialized at module load; each full
// ---- execution restores zeros at the end, so graph replays stay correct) ----
__device__ __align__(16) float g_protoSum[DDIM];
__device__ __align__(16) float g_proto[DDIM];
__device__ float    g_protoNorm;
__device__ int      g_entCount;
__device__ int      g_nzCount;
__device__ float    g_simSum;
__device__ int      g_isI64;
__device__ unsigned g_t1;
__device__ unsigned g_t2;

// ---------------------------------------------------------------------------
// K1: dtype detect + proto accumulation + (last block) finalize proto & norm.
// 256 blocks x 256 threads; warp owns 16 rows; only entity rows are read.
// ---------------------------------------------------------------------------
__global__ __launch_bounds__(256) void k_proto(const float* __restrict__ logits,
                                               const void*  __restrict__ labels,
                                               const int*   __restrict__ entity_ptr) {
    __shared__ float s_acc[DDIM];
    __shared__ int   s_flag;
    __shared__ int   s_ent[8];
    __shared__ bool  s_last;

    const int tid  = threadIdx.x;
    const int lane = tid & 31;
    const int wid  = tid >> 5;

    // -- dtype detection: block reads 128 consecutive int32 words of the
    //    first 32768 words (safe under both dtypes). If labels are int32,
    //    the 64 odd-indexed words are 64 random labels in [0,10): the chance
    //    they are all zero is 1e-64. If int64 (LE, values<2^31), odd words
    //    (high halves) are all zero.
    if (tid == 0) s_flag = 0;
    for (int d = tid; d < DDIM; d += 256) s_acc[d] = 0.0f;
    __syncthreads();
    {
        int w = ((const int*)labels)[blockIdx.x * 128 + (tid & 127)];
        if ((tid & 1) && w) atomicOr(&s_flag, 1);
    }
    __syncthreads();
    const bool isI64 = (s_flag == 0);
    if (blockIdx.x == 0 && tid == 0) g_isI64 = isI64 ? 1 : 0;

    const int entity_id = *entity_ptr;     // low 32 bits valid for i32/i64
    const int rowBase   = blockIdx.x * 128 + wid * 16;

    // prefetch this warp's 16 labels (one load per lane, broadcast via shfl)
    int myLab = 0;
    if (lane < 16) {
        const int r = rowBase + lane;
        myLab = isI64 ? (int)((const long long*)labels)[r]
                      : ((const int*)labels)[r];
    }

    float4 a0 = {0,0,0,0}, a1 = a0, a2 = a0, a3 = a0, a4 = a0, a5 = a0;
    int entLocal = 0;

    #pragma unroll 1
    for (int k = 0; k < 16; ++k) {
        const int lab = __shfl_sync(0xFFFFFFFFu, myLab, k);
        const int row = rowBase + k;
        if (lab == entity_id && (row & (SLEN - 1)) != 0) {
            entLocal++;                                  // uniform per warp
            const float4* __restrict__ r4 =
                (const float4*)(logits + (size_t)row * DDIM);
            float4 v;
            v = r4[lane      ]; a0.x+=v.x; a0.y+=v.y; a0.z+=v.z; a0.w+=v.w;
            v = r4[lane +  32]; a1.x+=v.x; a1.y+=v.y; a1.z+=v.z; a1.w+=v.w;
            v = r4[lane +  64]; a2.x+=v.x; a2.y+=v.y; a2.z+=v.z; a2.w+=v.w;
            v = r4[lane +  96]; a3.x+=v.x; a3.y+=v.y; a3.z+=v.z; a3.w+=v.w;
            v = r4[lane + 128]; a4.x+=v.x; a4.y+=v.y; a4.z+=v.z; a4.w+=v.w;
            v = r4[lane + 160]; a5.x+=v.x; a5.y+=v.y; a5.z+=v.z; a5.w+=v.w;
        }
    }

    // warp-register partials -> shared accumulator (spread-address atomics)
    {
        float* s = s_acc;
        atomicAdd(&s[4*(lane      )+0], a0.x); atomicAdd(&s[4*(lane      )+1], a0.y);
        atomicAdd(&s[4*(lane      )+2], a0.z); atomicAdd(&s[4*(lane      )+3], a0.w);
        atomicAdd(&s[4*(lane +  32)+0], a1.x); atomicAdd(&s[4*(lane +  32)+1], a1.y);
        atomicAdd(&s[4*(lane +  32)+2], a1.z); atomicAdd(&s[4*(lane +  32)+3], a1.w);
        atomicAdd(&s[4*(lane +  64)+0], a2.x); atomicAdd(&s[4*(lane +  64)+1], a2.y);
        atomicAdd(&s[4*(lane +  64)+2], a2.z); atomicAdd(&s[4*(lane +  64)+3], a2.w);
        atomicAdd(&s[4*(lane +  96)+0], a3.x); atomicAdd(&s[4*(lane +  96)+1], a3.y);
        atomicAdd(&s[4*(lane +  96)+2], a3.z); atomicAdd(&s[4*(lane +  96)+3], a3.w);
        atomicAdd(&s[4*(lane + 128)+0], a4.x); atomicAdd(&s[4*(lane + 128)+1], a4.y);
        atomicAdd(&s[4*(lane + 128)+2], a4.z); atomicAdd(&s[4*(lane + 128)+3], a4.w);
        atomicAdd(&s[4*(lane + 160)+0], a5.x); atomicAdd(&s[4*(lane + 160)+1], a5.y);
        atomicAdd(&s[4*(lane + 160)+2], a5.z); atomicAdd(&s[4*(lane + 160)+3], a5.w);
    }
    if (lane == 0) s_ent[wid] = entLocal;
    __syncthreads();

    for (int d = tid; d < DDIM; d += 256)
        atomicAdd(&g_protoSum[d], s_acc[d]);
    if (tid == 0) {
        int e = 0;
        #pragma unroll
        for (int i = 0; i < 8; ++i) e += s_ent[i];
        if (e) atomicAdd(&g_entCount, e);
    }

    // last-block finalize: proto = sum / max(cnt,1), protoNorm = ||proto||
    __threadfence();
    if (tid == 0) {
        unsigned t = atomicAdd(&g_t1, 1u);
        s_last = (t == (unsigned)(gridDim.x - 1));
    }
    __syncthreads();
    if (s_last) {
        const float inv = 1.0f / fmaxf((float)g_entCount, 1.0f);
        float ss = 0.0f;
        for (int d = tid; d < DDIM; d += 256) {
            float p = g_protoSum[d] * inv;
            g_proto[d] = p;
            ss += p * p;
        }
        __syncthreads();           // s_acc reuse barrier
        s_acc[tid] = ss;
        __syncthreads();
        for (int off = 128; off > 0; off >>= 1) {
            if (tid < off) s_acc[tid] += s_acc[tid + off];
            __syncthreads();
        }
        if (tid == 0) {
            g_protoNorm = sqrtf(s_acc[0]);
            g_t1 = 0;              // reset ticket for next replay
        }
    }
}

// ---------------------------------------------------------------------------
// K2 (hot): warp per row, 8 rows per warp, proto in registers.
// Labels prefetched per warp; row loads unconditional + fully unrolled so
// ptxas can front-batch them (high MLP); contribution masked on lane 0.
// Last block writes d_out and re-zeros all device state.
// 1024 blocks x 128 threads.
// ---------------------------------------------------------------------------
__global__ __launch_bounds__(128) void k_main(const float* __restrict__ logits,
                                              const void*  __restrict__ labels,
                                              float* __restrict__ d_out) {
    __shared__ float s_sum[4];
    __shared__ int   s_nz[4];
    __shared__ bool  s_last;

    const int tid  = threadIdx.x;
    const int lane = tid & 31;
    const int wid  = tid >> 5;
    const int gw   = blockIdx.x * 4 + wid;      // 0..4095
    const bool isI64 = (g_isI64 != 0);

    // proto in registers (finalized by k_proto; stream order guarantees it)
    const float4* __restrict__ proto4 = (const float4*)g_proto;
    const float4 p0 = proto4[lane      ];
    const float4 p1 = proto4[lane +  32];
    const float4 p2 = proto4[lane +  64];
    const float4 p3 = proto4[lane +  96];
    const float4 p4 = proto4[lane + 128];
    const float4 p5 = proto4[lane + 160];
    const float  protoNorm = g_protoNorm;

    // prefetch this warp's 8 labels
    int myLab = 0;
    if (lane < 8) {
        const int r = gw * 8 + lane;
        myLab = isI64 ? (int)((const long long*)labels)[r]
                      : ((const int*)labels)[r];
    }

    float simLocal = 0.0f;
    int   nzLocal  = 0;

    #pragma unroll
    for (int k = 0; k < 8; ++k) {
        const int lab = __shfl_sync(0xFFFFFFFFu, myLab, k);
        const float4* __restrict__ row4 =
            (const float4*)(logits + (size_t)(gw * 8 + k) * DDIM);
        const float4 v0 = row4[lane      ];
        const float4 v1 = row4[lane +  32];
        const float4 v2 = row4[lane +  64];
        const float4 v3 = row4[lane +  96];
        const float4 v4 = row4[lane + 128];
        const float4 v5 = row4[lane + 160];

        float dot =
            v0.x*p0.x + v0.y*p0.y + v0.z*p0.z + v0.w*p0.w +
            v1.x*p1.x + v1.y*p1.y + v1.z*p1.z + v1.w*p1.w +
            v2.x*p2.x + v2.y*p2.y + v2.z*p2.z + v2.w*p2.w +
            v3.x*p3.x + v3.y*p3.y + v3.z*p3.z + v3.w*p3.w +
            v4.x*p4.x + v4.y*p4.y + v4.z*p4.z + v4.w*p4.w +
            v5.x*p5.x + v5.y*p5.y + v5.z*p5.z + v5.w*p5.w;
        float nrm =
            v0.x*v0.x + v0.y*v0.y + v0.z*v0.z + v0.w*v0.w +
            v1.x*v1.x + v1.y*v1.y + v1.z*v1.z + v1.w*v1.w +
            v2.x*v2.x + v2.y*v2.y + v2.z*v2.z + v2.w*v2.w +
            v3.x*v3.x + v3.y*v3.y + v3.z*v3.z + v3.w*v3.w +
            v4.x*v4.x + v4.y*v4.y + v4.z*v4.z + v4.w*v4.w +
            v5.x*v5.x + v5.y*v5.y + v5.z*v5.z + v5.w*v5.w;

        #pragma unroll
        for (int off = 16; off > 0; off >>= 1) {
            dot += __shfl_xor_sync(0xFFFFFFFFu, dot, off);
            nrm += __shfl_xor_sync(0xFFFFFFFFu, nrm, off);
        }
        if (lane == 0 && lab != 0) {
            nzLocal++;
            simLocal += dot / fmaxf(sqrtf(nrm) * protoNorm, EPSV);
        }
    }

    if (lane == 0) { s_sum[wid] = simLocal; s_nz[wid] = nzLocal; }
    __syncthreads();
    if (tid == 0) {
        float bs = s_sum[0] + s_sum[1] + s_sum[2] + s_sum[3];
        int   bn = s_nz[0] + s_nz[1] + s_nz[2] + s_nz[3];
        atomicAdd(&g_simSum, bs);
        atomicAdd(&g_nzCount, bn);
    }

    // last block: produce output, then restore zeroed state for next replay
    __threadfence();
    if (tid == 0) {
        unsigned t = atomicAdd(&g_t2, 1u);
        s_last = (t == (unsigned)(gridDim.x - 1));
    }
    __syncthreads();
    if (s_last) {
        if (tid == 0) {
            d_out[0] = g_simSum / fmaxf((float)g_nzCount, 1.0f);
            g_simSum  = 0.0f;
            g_nzCount = 0;
            g_entCount = 0;
            g_protoNorm = 0.0f;
            g_t2 = 0;
        }
        for (int d = tid; d < DDIM; d += 128) g_protoSum[d] = 0.0f;
    }
}

extern "C" void kernel_launch(void* const* d_in, const int* in_sizes, int n_in,
                              void* d_out, int out_size) {
    const float* logits     = (const float*)d_in[0];
    const void*  labels     = d_in[1];
    const int*   entity_ptr = (const int*)d_in[2];
    (void)n_in; (void)in_sizes; (void)out_size;

    k_proto<<<PROTO_BLOCKS, 256>>>(logits, labels, entity_ptr);
    k_main<<<MAIN_BLOCKS, 128>>>(logits, labels, (float*)d_out);
}